// round 7
// baseline (speedup 1.0000x reference)
#include <cuda_runtime.h>

// ---------------------------------------------------------------------------
// StateBank: 3-level top-k attention read.
//   scores_L = Q @ K_L^T / 32 + sal_L          (fp32, exact)
//   top-32 per (b,t) row per level, softmax, weighted gather of V_L rows,
//   summed over levels.
//
// Phase 1: fp32 SGEMM (FFMA2 / fma.rn.f32x2 packed) -> g_scores scratch.
// Phase 2: per-row top-32 extraction + softmax + V gather (one CTA per row).
// ---------------------------------------------------------------------------

#define DDIM 1024
#define BM 128
#define BN 64
#define BK 16
#define GEMM_THREADS 256
#define TOPK 32

// Scratch: 8192 rows x 14336 score columns (fp32) = 470 MB.
static __device__ float g_scores[(size_t)8192 * (size_t)14336];

__device__ __forceinline__ unsigned long long pack2(float lo, float hi) {
    unsigned long long r;
    asm("mov.b64 %0, {%1, %2};" : "=l"(r) : "f"(lo), "f"(hi));
    return r;
}
__device__ __forceinline__ void unpack2(unsigned long long v, float& lo, float& hi) {
    asm("mov.b64 {%0, %1}, %2;" : "=f"(lo), "=f"(hi) : "l"(v));
}
// d.lo += a.lo*b.lo ; d.hi += a.hi*b.hi   (packed fp32x2 FMA, FFMA2 in SASS)
__device__ __forceinline__ void fma2(unsigned long long& d,
                                     unsigned long long a,
                                     unsigned long long b) {
    asm("fma.rn.f32x2 %0, %1, %2, %0;" : "+l"(d) : "l"(a), "l"(b));
}

__device__ __forceinline__ float neg_inf_f() { return __int_as_float(0xff800000); }

// ---------------------------------------------------------------------------
// Phase 1: C[m][n] = (sum_k Q[m][k]*K[n][k]) * (1/32) + sal[n]
// Tile 128x64x16, 256 threads, per-thread 8x4 microtile done as 4 row-pairs
// (f32x2) x 4 cols. B is stored duplicated ((b,b) pairs) in smem so the inner
// loop is 4x LDS + 16x FFMA2 with no repacking MOVs.
// ---------------------------------------------------------------------------
__global__ __launch_bounds__(GEMM_THREADS)
void score_gemm_kernel(const float* __restrict__ Q,
                       const float* __restrict__ Kmat,
                       const float* __restrict__ sal,
                       int Ntot, int col_off)
{
    __shared__ __align__(16) float As[BK][BM + 4];                 // k-major A
    __shared__ __align__(16) unsigned long long Bs[BK][BN + 2];    // k-major B, (b,b)

    const int tid = threadIdx.x;
    const int tx  = tid & 15;       // 0..15 -> col group
    const int ty  = tid >> 4;       // 0..15 -> row group
    const int m0  = ty * 8;
    const int n0  = tx * 4;
    const int blockM = blockIdx.y * BM;
    const int blockN = blockIdx.x * BN;

    const int ldRow = tid >> 2;        // 0..63
    const int ldK   = (tid & 3) * 4;   // 0,4,8,12

    const float* Aptr0 = Q    + (size_t)(blockM + ldRow) * DDIM + ldK;
    const float* Aptr1 = Aptr0 + (size_t)64 * DDIM;
    const float* Bptr  = Kmat + (size_t)(blockN + ldRow) * DDIM + ldK;

    unsigned long long acc[4][4];
#pragma unroll
    for (int r = 0; r < 4; r++)
#pragma unroll
        for (int j = 0; j < 4; j++) acc[r][j] = 0ULL;  // (0.0f, 0.0f)

    for (int kt = 0; kt < DDIM; kt += BK) {
        float4 a0 = *(const float4*)(Aptr0 + kt);
        float4 a1 = *(const float4*)(Aptr1 + kt);
        float4 b0 = *(const float4*)(Bptr  + kt);

        As[ldK + 0][ldRow]      = a0.x;
        As[ldK + 1][ldRow]      = a0.y;
        As[ldK + 2][ldRow]      = a0.z;
        As[ldK + 3][ldRow]      = a0.w;
        As[ldK + 0][ldRow + 64] = a1.x;
        As[ldK + 1][ldRow + 64] = a1.y;
        As[ldK + 2][ldRow + 64] = a1.z;
        As[ldK + 3][ldRow + 64] = a1.w;
        Bs[ldK + 0][ldRow] = pack2(b0.x, b0.x);
        Bs[ldK + 1][ldRow] = pack2(b0.y, b0.y);
        Bs[ldK + 2][ldRow] = pack2(b0.z, b0.z);
        Bs[ldK + 3][ldRow] = pack2(b0.w, b0.w);
        __syncthreads();

#pragma unroll
        for (int k = 0; k < BK; k++) {
            const unsigned long long* arow =
                reinterpret_cast<const unsigned long long*>(&As[k][m0]);
            unsigned long long ap0 = arow[0];
            unsigned long long ap1 = arow[1];
            unsigned long long ap2 = arow[2];
            unsigned long long ap3 = arow[3];
            unsigned long long bp0 = Bs[k][n0 + 0];
            unsigned long long bp1 = Bs[k][n0 + 1];
            unsigned long long bp2 = Bs[k][n0 + 2];
            unsigned long long bp3 = Bs[k][n0 + 3];
            fma2(acc[0][0], ap0, bp0); fma2(acc[0][1], ap0, bp1);
            fma2(acc[0][2], ap0, bp2); fma2(acc[0][3], ap0, bp3);
            fma2(acc[1][0], ap1, bp0); fma2(acc[1][1], ap1, bp1);
            fma2(acc[1][2], ap1, bp2); fma2(acc[1][3], ap1, bp3);
            fma2(acc[2][0], ap2, bp0); fma2(acc[2][1], ap2, bp1);
            fma2(acc[2][2], ap2, bp2); fma2(acc[2][3], ap2, bp3);
            fma2(acc[3][0], ap3, bp0); fma2(acc[3][1], ap3, bp1);
            fma2(acc[3][2], ap3, bp2); fma2(acc[3][3], ap3, bp3);
        }
        __syncthreads();
    }

    const float scale = 0.03125f;  // 1/sqrt(1024), exact
    float sv[4];
#pragma unroll
    for (int j = 0; j < 4; j++) sv[j] = sal[blockN + n0 + j];

#pragma unroll
    for (int r = 0; r < 4; r++) {
        float lo[4], hi[4];
#pragma unroll
        for (int j = 0; j < 4; j++) unpack2(acc[r][j], lo[j], hi[j]);
        size_t base = (size_t)(blockM + m0 + 2 * r) * (size_t)Ntot
                      + (size_t)(col_off + blockN + n0);
        float4 v0 = make_float4(fmaf(lo[0], scale, sv[0]), fmaf(lo[1], scale, sv[1]),
                                fmaf(lo[2], scale, sv[2]), fmaf(lo[3], scale, sv[3]));
        float4 v1 = make_float4(fmaf(hi[0], scale, sv[0]), fmaf(hi[1], scale, sv[1]),
                                fmaf(hi[2], scale, sv[2]), fmaf(hi[3], scale, sv[3]));
        *reinterpret_cast<float4*>(&g_scores[base])        = v0;
        *reinterpret_cast<float4*>(&g_scores[base + Ntot]) = v1;
    }
}

// ---------------------------------------------------------------------------
// Phase 2: one CTA per (b,t) row. For each level: load score row to smem,
// extract top-32 by repeated argmax (each thread caches its local stride-max
// and only the owner of the extracted element rescans), softmax, then gather
// 32 V rows (float4-coalesced) into a register accumulator; sum 3 levels.
// ---------------------------------------------------------------------------
__global__ __launch_bounds__(256)
void topk_gather_kernel(const float* __restrict__ V0,
                        const float* __restrict__ V1,
                        const float* __restrict__ V2,
                        float* __restrict__ out,
                        int Ntot, int S0, int S1, int S2)
{
    __shared__ float s[8192];
    __shared__ float rv[8];
    __shared__ int   ri[8];
    __shared__ float selv[TOPK];
    __shared__ int   seli[TOPK];
    __shared__ float w[TOPK];

    const int tid  = threadIdx.x;
    const int lane = tid & 31;
    const int wid  = tid >> 5;
    const int row  = blockIdx.x;
    const float NEG_INF = neg_inf_f();

    float4 acc = make_float4(0.f, 0.f, 0.f, 0.f);

    const float* Vp[3] = {V0, V1, V2};
    const int Sz[3] = {S0, S1, S2};
    const int Of[3] = {0, S0, S0 + S1};

    for (int lev = 0; lev < 3; lev++) {
        const int S = Sz[lev];
        const float* sc = g_scores + (size_t)row * (size_t)Ntot + Of[lev];
        for (int i = tid; i < S; i += 256) s[i] = sc[i];
        __syncthreads();

        // per-thread local max over its strided slice
        float best = NEG_INF; int bi = -1;
        for (int i = tid; i < S; i += 256) {
            float v = s[i];
            if (v > best) { best = v; bi = i; }
        }

        for (int sel = 0; sel < TOPK; sel++) {
            // warp argmax (val desc, idx asc tie-break = lax.top_k semantics)
            float v = best; int idx = bi;
#pragma unroll
            for (int o = 16; o > 0; o >>= 1) {
                float ov = __shfl_xor_sync(0xffffffffu, v, o);
                int   oi = __shfl_xor_sync(0xffffffffu, idx, o);
                if (ov > v || (ov == v && oi >= 0 && (unsigned)oi < (unsigned)idx)) {
                    v = ov; idx = oi;
                }
            }
            if (lane == 0) { rv[wid] = v; ri[wid] = idx; }
            __syncthreads();
            if (tid == 0) {
                float gv = rv[0]; int gi = ri[0];
#pragma unroll
                for (int q = 1; q < 8; q++) {
                    if (rv[q] > gv ||
                        (rv[q] == gv && ri[q] >= 0 && (unsigned)ri[q] < (unsigned)gi)) {
                        gv = rv[q]; gi = ri[q];
                    }
                }
                selv[sel] = gv; seli[sel] = gi;
                s[gi] = NEG_INF;  // mask extracted element
            }
            __syncthreads();
            // only the owner of the extracted element rescans its slice
            if (bi == seli[sel]) {
                best = NEG_INF; bi = -1;
                for (int i = tid; i < S; i += 256) {
                    float vv = s[i];
                    if (vv > best) { best = vv; bi = i; }
                }
            }
        }

        // softmax over the 32 (descending) selected scores; max = selv[0]
        if (tid < TOPK) {
            float e = expf(selv[tid] - selv[0]);
            float sum = e;
#pragma unroll
            for (int o = 16; o > 0; o >>= 1) sum += __shfl_xor_sync(0xffffffffu, sum, o);
            w[tid] = e / sum;
        }
        __syncthreads();

        // gather: thread t owns dims [4t, 4t+4); 32 coalesced float4 row reads
        const float* V = Vp[lev];
#pragma unroll 8
        for (int i = 0; i < TOPK; i++) {
            float wi = w[i];
            const float4 vv =
                *reinterpret_cast<const float4*>(V + (size_t)seli[i] * DDIM + tid * 4);
            acc.x = fmaf(wi, vv.x, acc.x);
            acc.y = fmaf(wi, vv.y, acc.y);
            acc.z = fmaf(wi, vv.z, acc.z);
            acc.w = fmaf(wi, vv.w, acc.w);
        }
        __syncthreads();  // protect s[] / selv / w before next level
    }

    *reinterpret_cast<float4*>(out + (size_t)row * DDIM + tid * 4) = acc;
}

// ---------------------------------------------------------------------------
// Launch. Inputs (metadata order): queries, keys0, values0, sal0,
// keys1, values1, sal1, keys2, values2, sal2, [top_k].
// top_k is fixed at 32 (all levels have >= 32 keys).
// ---------------------------------------------------------------------------
extern "C" void kernel_launch(void* const* d_in, const int* in_sizes, int n_in,
                              void* d_out, int out_size)
{
    const float* Q    = (const float*)d_in[0];
    const float* K0   = (const float*)d_in[1];
    const float* Vv0  = (const float*)d_in[2];
    const float* sal0 = (const float*)d_in[3];
    const float* K1   = (const float*)d_in[4];
    const float* Vv1  = (const float*)d_in[5];
    const float* sal1 = (const float*)d_in[6];
    const float* K2   = (const float*)d_in[7];
    const float* Vv2  = (const float*)d_in[8];
    const float* sal2 = (const float*)d_in[9];
    float* out = (float*)d_out;

    const int M  = in_sizes[0] / DDIM;   // 8192 query rows (B*T)
    const int S0 = in_sizes[1] / DDIM;   // 8192
    const int S1 = in_sizes[4] / DDIM;   // 4096
    const int S2 = in_sizes[7] / DDIM;   // 2048
    const int Ntot = S0 + S1 + S2;       // 14336

    score_gemm_kernel<<<dim3(S0 / BN, M / BM), GEMM_THREADS>>>(Q, K0, sal0, Ntot, 0);
    score_gemm_kernel<<<dim3(S1 / BN, M / BM), GEMM_THREADS>>>(Q, K1, sal1, Ntot, S0);
    score_gemm_kernel<<<dim3(S2 / BN, M / BM), GEMM_THREADS>>>(Q, K2, sal2, Ntot, S0 + S1);
    topk_gather_kernel<<<M, 256>>>(Vv0, Vv1, Vv2, out, Ntot, S0, S1, S2);
}